// round 7
// baseline (speedup 1.0000x reference)
#include <cuda_runtime.h>
#include <math.h>

// ---------------------------------------------------------------------------
// Problem constants
// ---------------------------------------------------------------------------
#define LAYERS 4
#define NH     16
#define DM     1024
#define VO     32000
#define TT     2048
#define BBATCH 2
#define HDIM   64
#define BTOK   (BBATCH*TT)   // 4096

// ---------------------------------------------------------------------------
// Scratch (static __device__ arrays: the sanctioned no-alloc path)
// ---------------------------------------------------------------------------
__device__ float g_x   [(size_t)BTOK * DM];          // residual stream   16 MB
__device__ float g_h   [(size_t)BTOK * DM];          // layernorm output  16 MB
__device__ float g_qkv [(size_t)BTOK * 3 * DM];      // qkv               48 MB
__device__ float g_attn[(size_t)BTOK * DM];          // attn out          16 MB
__device__ float g_mid [(size_t)BTOK * 4 * DM];      // ffn mid           64 MB
__device__ float g_sc  [(size_t)BBATCH * NH * TT * TT]; // scores         536 MB

// ---------------------------------------------------------------------------
// Helpers
// ---------------------------------------------------------------------------
__device__ __forceinline__ float gelu_exact(float x) {
    return 0.5f * x * (1.0f + erff(x * 0.70710678118654752440f));
}

template <bool DOMAX>
__device__ __forceinline__ float block_reduce(float v) {
    __shared__ float sh[33];
    const int lane = threadIdx.x & 31;
    const int wid  = threadIdx.x >> 5;
#pragma unroll
    for (int o = 16; o; o >>= 1) {
        float t = __shfl_xor_sync(0xffffffffu, v, o);
        v = DOMAX ? fmaxf(v, t) : (v + t);
    }
    if (lane == 0) sh[wid] = v;
    __syncthreads();
    const int nw = blockDim.x >> 5;
    if (wid == 0) {
        float t = (lane < nw) ? sh[lane] : (DOMAX ? -3.4e38f : 0.0f);
#pragma unroll
        for (int o = 16; o; o >>= 1) {
            float u = __shfl_xor_sync(0xffffffffu, t, o);
            t = DOMAX ? fmaxf(t, u) : (t + u);
        }
        if (lane == 0) sh[32] = t;
    }
    __syncthreads();
    float r = sh[32];
    __syncthreads();   // safe reuse of sh on subsequent calls
    return r;
}

// ---------------------------------------------------------------------------
// Embedding: x[b,t,:] = tok_emb[id] + pos_emb[t] + context_emb[b]
// grid = BTOK blocks, 256 threads, float4 per thread
// ---------------------------------------------------------------------------
__global__ void embed_k(const int* __restrict__ ids,
                        const float* __restrict__ tok,
                        const float* __restrict__ pos,
                        const float* __restrict__ ctx,
                        float* __restrict__ x) {
    const int bt = blockIdx.x;
    const int b  = bt / TT;
    const int t  = bt - b * TT;
    const int id = ids[bt];
    const int d  = threadIdx.x * 4;
    const float4 a = *(const float4*)(tok + (size_t)id * DM + d);
    const float4 p = *(const float4*)(pos + (size_t)t  * DM + d);
    const float4 c = *(const float4*)(ctx + (size_t)b  * DM + d);
    float4 r;
    r.x = a.x + p.x + c.x; r.y = a.y + p.y + c.y;
    r.z = a.z + p.z + c.z; r.w = a.w + p.w + c.w;
    *(float4*)(x + (size_t)bt * DM + d) = r;
}

// ---------------------------------------------------------------------------
// LayerNorm over last dim D=1024. One block (256 threads) per row.
// ---------------------------------------------------------------------------
__global__ void layernorm_k(const float* __restrict__ xin,
                            float* __restrict__ yout,
                            const float* __restrict__ w,
                            const float* __restrict__ b) {
    const size_t row = blockIdx.x;
    const float* xr = xin + row * DM;
    float*       yr = yout + row * DM;
    const int d = threadIdx.x * 4;

    const float4 v = *(const float4*)(xr + d);
    float s  = v.x + v.y + v.z + v.w;
    float s2 = v.x*v.x + v.y*v.y + v.z*v.z + v.w*v.w;
    s  = block_reduce<false>(s);
    s2 = block_reduce<false>(s2);
    const float mean = s * (1.0f / DM);
    const float var  = s2 * (1.0f / DM) - mean * mean;
    const float rstd = rsqrtf(var + 1e-5f);

    const float4 ww = *(const float4*)(w + d);
    const float4 bb = *(const float4*)(b + d);
    float4 r;
    r.x = (v.x - mean) * rstd * ww.x + bb.x;
    r.y = (v.y - mean) * rstd * ww.y + bb.y;
    r.z = (v.z - mean) * rstd * ww.z + bb.z;
    r.w = (v.w - mean) * rstd * ww.w + bb.w;
    *(float4*)(yr + d) = r;
}

// ---------------------------------------------------------------------------
// Generic fp32 GEMM:  C[m,n] = epilogue( scale * sum_k A[m,k]*B(n,k) )
//   BTR=true : B(n,k) = B[n*ldb + k]   (NT: weight matrices [N,K] row-major)
//   BTR=false: B(n,k) = B[k*ldb + n]   (NN: P@V)
// Per-z (batch*head) pointer offsets: off = (z/nheads)*s?b + (z%nheads)*s?h
// causal_mode: 0 none; 1 skip tiles strictly above diagonal (scores);
//              2 clip K loop to m0+BM (P@V with zeroed upper triangle)
// Epilogue: *scale, +bias[n], optional exact GELU, optional residual add.
// All call sites use M%BM==0, N%BN==0, K%BK==0 (verified statically by shapes).
// ---------------------------------------------------------------------------
template <int BM, int BN, int BK, int TM, int TN, int NTH, bool BTR, bool DOGELU>
__global__ __launch_bounds__(NTH, 2)
void gemm_k(const float* __restrict__ A, long lda, long sAb, long sAh,
            const float* __restrict__ B, long ldb, long sBb, long sBh,
            float* __restrict__ C,       long ldc, long sCb, long sCh,
            int M, int N, int K, int nheads,
            const float* __restrict__ bias,
            const float* __restrict__ resid,
            float scale, int causal_mode) {
    const int z  = blockIdx.z;
    const int bb = z / nheads;
    const int hh = z - bb * nheads;
    A += (size_t)bb * sAb + (size_t)hh * sAh;
    B += (size_t)bb * sBb + (size_t)hh * sBh;
    const size_t coff = (size_t)bb * sCb + (size_t)hh * sCh;
    C += coff;
    if (resid) resid += coff;

    const int m0 = blockIdx.y * BM;
    const int n0 = blockIdx.x * BN;
    if (causal_mode == 1 && n0 > m0 + BM - 1) return;   // fully masked tile
    int Keff = K;
    if (causal_mode == 2) Keff = min(K, m0 + BM);       // P is 0 beyond row idx

    __shared__ float As[BK][BM + 4];
    __shared__ float Bs[BK][BN + 4];

    const int tid = threadIdx.x;
    const int tx  = tid % (BN / TN);
    const int ty  = tid / (BN / TN);

    float acc[TM][TN];
#pragma unroll
    for (int i = 0; i < TM; i++)
#pragma unroll
        for (int j = 0; j < TN; j++) acc[i][j] = 0.0f;

    for (int k0 = 0; k0 < Keff; k0 += BK) {
        // --- load A tile (BM x BK), transpose into As[BK][BM] ---
#pragma unroll
        for (int i = tid; i < BM * BK / 4; i += NTH) {
            const int r  = i / (BK / 4);
            const int c4 = i - r * (BK / 4);
            const float4 v = *(const float4*)(A + (size_t)(m0 + r) * lda + k0 + c4 * 4);
            As[c4 * 4 + 0][r] = v.x;
            As[c4 * 4 + 1][r] = v.y;
            As[c4 * 4 + 2][r] = v.z;
            As[c4 * 4 + 3][r] = v.w;
        }
        // --- load B tile into Bs[BK][BN] ---
        if (BTR) {
#pragma unroll
            for (int i = tid; i < BN * BK / 4; i += NTH) {
                const int r  = i / (BK / 4);
                const int c4 = i - r * (BK / 4);
                const float4 v = *(const float4*)(B + (size_t)(n0 + r) * ldb + k0 + c4 * 4);
                Bs[c4 * 4 + 0][r] = v.x;
                Bs[c4 * 4 + 1][r] = v.y;
                Bs[c4 * 4 + 2][r] = v.z;
                Bs[c4 * 4 + 3][r] = v.w;
            }
        } else {
#pragma unroll
            for (int i = tid; i < BK * BN / 4; i += NTH) {
                const int r  = i / (BN / 4);
                const int c4 = i - r * (BN / 4);
                const float4 v = *(const float4*)(B + (size_t)(k0 + r) * ldb + n0 + c4 * 4);
                *(float4*)&Bs[r][c4 * 4] = v;
            }
        }
        __syncthreads();

#pragma unroll
        for (int k = 0; k < BK; k++) {
            float a[TM], bf[TN];
#pragma unroll
            for (int i = 0; i < TM; i += 4)
                *(float4*)&a[i] = *(const float4*)&As[k][ty * TM + i];
#pragma unroll
            for (int j = 0; j < TN; j += 4)
                *(float4*)&bf[j] = *(const float4*)&Bs[k][tx * TN + j];
#pragma unroll
            for (int i = 0; i < TM; i++)
#pragma unroll
                for (int j = 0; j < TN; j++)
                    acc[i][j] = fmaf(a[i], bf[j], acc[i][j]);
        }
        __syncthreads();
    }

    // --- epilogue ---
#pragma unroll
    for (int i = 0; i < TM; i++) {
        const int m = m0 + ty * TM + i;
#pragma unroll
        for (int j = 0; j < TN; j++) {
            const int n = n0 + tx * TN + j;
            float v = acc[i][j] * scale;
            if (bias)  v += bias[n];
            if (DOGELU) v = gelu_exact(v);
            if (resid) v += resid[(size_t)m * ldc + n];
            C[(size_t)m * ldc + n] = v;
        }
    }
}

// ---------------------------------------------------------------------------
// Causal softmax in place over scores rows. grid=(T, B*H), 256 threads.
// Normalizes j in [0, i]; writes 0 for j in (i, T) so P@V can run dense tiles.
// ---------------------------------------------------------------------------
__global__ void softmax_k(float* __restrict__ S) {
    const int  i = blockIdx.x;
    const long z = blockIdx.y;
    float* row = S + (z * (long)TT + i) * (long)TT;
    const int len = i + 1;

    float m = -3.4e38f;
    for (int j = threadIdx.x; j < len; j += blockDim.x) m = fmaxf(m, row[j]);
    m = block_reduce<true>(m);

    float s = 0.0f;
    for (int j = threadIdx.x; j < len; j += blockDim.x) {
        const float e = __expf(row[j] - m);
        row[j] = e;
        s += e;
    }
    s = block_reduce<false>(s);
    const float inv = 1.0f / s;

    for (int j = threadIdx.x; j < len; j += blockDim.x) row[j] *= inv;
    for (int j = len + threadIdx.x; j < TT; j += blockDim.x) row[j] = 0.0f;
}

// ---------------------------------------------------------------------------
// Host orchestration
// ---------------------------------------------------------------------------
extern "C" void kernel_launch(void* const* d_in, const int* in_sizes, int n_in,
                              void* d_out, int out_size) {
    (void)in_sizes; (void)n_in; (void)out_size;
    const int*   ids   = (const int*)  d_in[0];
    const float* ctx   = (const float*)d_in[1];
    const float* tok   = (const float*)d_in[2];
    const float* pos   = (const float*)d_in[3];
    const float* qkvw  = (const float*)d_in[4];
    const float* qkvb  = (const float*)d_in[5];
    const float* projw = (const float*)d_in[6];
    const float* projb = (const float*)d_in[7];
    const float* ln1w  = (const float*)d_in[8];
    const float* ln1b  = (const float*)d_in[9];
    const float* ln2w  = (const float*)d_in[10];
    const float* ln2b  = (const float*)d_in[11];
    const float* f1w   = (const float*)d_in[12];
    const float* f1b   = (const float*)d_in[13];
    const float* f2w   = (const float*)d_in[14];
    const float* f2b   = (const float*)d_in[15];
    const float* lnfw  = (const float*)d_in[16];
    const float* lnfb  = (const float*)d_in[17];
    float* out = (float*)d_out;

    float *x, *h, *qkv, *attn, *mid, *sc;
    cudaGetSymbolAddress((void**)&x,    g_x);
    cudaGetSymbolAddress((void**)&h,    g_h);
    cudaGetSymbolAddress((void**)&qkv,  g_qkv);
    cudaGetSymbolAddress((void**)&attn, g_attn);
    cudaGetSymbolAddress((void**)&mid,  g_mid);
    cudaGetSymbolAddress((void**)&sc,   g_sc);

    const float attn_scale = 0.125f;  // 1/sqrt(64)

    embed_k<<<BTOK, 256>>>(ids, tok, pos, ctx, x);

    for (int l = 0; l < LAYERS; l++) {
        // ln1
        layernorm_k<<<BTOK, 256>>>(x, h, ln1w + (size_t)l * DM, ln1b + (size_t)l * DM);

        // qkv = h @ qkv_w^T + qkv_b      [4096, 3072]
        gemm_k<128,128,16,8,8,256,true,false><<<dim3(3*DM/128, BTOK/128, 1), 256>>>(
            h, DM, 0, 0,
            qkvw + (size_t)l * 3 * DM * DM, DM, 0, 0,
            qkv, 3*DM, 0, 0,
            BTOK, 3*DM, DM, 1,
            qkvb + (size_t)l * 3 * DM, nullptr, 1.0f, 0);

        // scores[z] = scale * Q @ K^T   (skip upper-triangle tiles)
        gemm_k<128,128,16,8,8,256,true,false><<<dim3(TT/128, TT/128, BBATCH*NH), 256>>>(
            qkv,        3*DM, (long)TT*3*DM, HDIM,
            qkv + DM,   3*DM, (long)TT*3*DM, HDIM,
            sc, TT, (long)NH*TT*TT, (long)TT*TT,
            TT, TT, HDIM, NH,
            nullptr, nullptr, attn_scale, 1);

        // causal softmax (zeros upper triangle)
        softmax_k<<<dim3(TT, BBATCH*NH), 256>>>(sc);

        // attn[z] = P @ V   (K loop clipped to m0+BM)
        gemm_k<128,64,16,8,4,256,false,false><<<dim3(1, TT/128, BBATCH*NH), 256>>>(
            sc, TT, (long)NH*TT*TT, (long)TT*TT,
            qkv + 2*DM, 3*DM, (long)TT*3*DM, HDIM,
            attn, DM, (long)TT*DM, HDIM,
            TT, HDIM, TT, NH,
            nullptr, nullptr, 1.0f, 2);

        // x += attn @ proj_w^T + proj_b
        gemm_k<128,128,16,8,8,256,true,false><<<dim3(DM/128, BTOK/128, 1), 256>>>(
            attn, DM, 0, 0,
            projw + (size_t)l * DM * DM, DM, 0, 0,
            x, DM, 0, 0,
            BTOK, DM, DM, 1,
            projb + (size_t)l * DM, x, 1.0f, 0);

        // ln2
        layernorm_k<<<BTOK, 256>>>(x, h, ln2w + (size_t)l * DM, ln2b + (size_t)l * DM);

        // mid = gelu(h @ f1_w^T + f1_b)   [4096, 4096]
        gemm_k<128,128,16,8,8,256,true,true><<<dim3(4*DM/128, BTOK/128, 1), 256>>>(
            h, DM, 0, 0,
            f1w + (size_t)l * 4 * DM * DM, DM, 0, 0,
            mid, 4*DM, 0, 0,
            BTOK, 4*DM, DM, 1,
            f1b + (size_t)l * 4 * DM, nullptr, 1.0f, 0);

        // x += mid @ f2_w^T + f2_b
        gemm_k<128,128,16,8,8,256,true,false><<<dim3(DM/128, BTOK/128, 1), 256>>>(
            mid, 4*DM, 0, 0,
            f2w + (size_t)l * DM * 4 * DM, 4*DM, 0, 0,
            x, DM, 0, 0,
            BTOK, DM, 4*DM, 1,
            f2b + (size_t)l * DM, x, 1.0f, 0);
    }

    // final layernorm
    layernorm_k<<<BTOK, 256>>>(x, h, lnfw, lnfb);

    // logits = h @ tok_emb^T   [4096, 32000]
    gemm_k<128,128,16,8,8,256,true,false><<<dim3(VO/128, BTOK/128, 1), 256>>>(
        h, DM, 0, 0,
        tok, DM, 0, 0,
        out, VO, 0, 0,
        BTOK, VO, DM, 1,
        nullptr, nullptr, 1.0f, 0);
}

// round 8
// speedup vs baseline: 1.0009x; 1.0009x over previous
#include <cuda_runtime.h>
#include <math.h>

// ---------------------------------------------------------------------------
// Problem constants
// ---------------------------------------------------------------------------
#define LAYERS 4
#define NH     16
#define DM     1024
#define VO     32000
#define TT     2048
#define BBATCH 2
#define HDIM   64
#define BTOK   (BBATCH*TT)   // 4096

// ---------------------------------------------------------------------------
// Scratch (static __device__ arrays: the sanctioned no-alloc path)
// ---------------------------------------------------------------------------
__device__ float g_x   [(size_t)BTOK * DM];          // residual stream   16 MB
__device__ float g_h   [(size_t)BTOK * DM];          // layernorm output  16 MB
__device__ float g_qkv [(size_t)BTOK * 3 * DM];      // qkv               48 MB
__device__ float g_attn[(size_t)BTOK * DM];          // attn out          16 MB
__device__ float g_mid [(size_t)BTOK * 4 * DM];      // ffn mid           64 MB
__device__ float g_sc  [(size_t)BBATCH * NH * TT * TT]; // scores         536 MB

// ---------------------------------------------------------------------------
// Helpers
// ---------------------------------------------------------------------------
__device__ __forceinline__ float gelu_exact(float x) {
    return 0.5f * x * (1.0f + erff(x * 0.70710678118654752440f));
}

template <bool DOMAX>
__device__ __forceinline__ float block_reduce(float v) {
    __shared__ float sh[33];
    const int lane = threadIdx.x & 31;
    const int wid  = threadIdx.x >> 5;
#pragma unroll
    for (int o = 16; o; o >>= 1) {
        float t = __shfl_xor_sync(0xffffffffu, v, o);
        v = DOMAX ? fmaxf(v, t) : (v + t);
    }
    if (lane == 0) sh[wid] = v;
    __syncthreads();
    const int nw = blockDim.x >> 5;
    if (wid == 0) {
        float t = (lane < nw) ? sh[lane] : (DOMAX ? -3.4e38f : 0.0f);
#pragma unroll
        for (int o = 16; o; o >>= 1) {
            float u = __shfl_xor_sync(0xffffffffu, t, o);
            t = DOMAX ? fmaxf(t, u) : (t + u);
        }
        if (lane == 0) sh[32] = t;
    }
    __syncthreads();
    float r = sh[32];
    __syncthreads();   // safe reuse of sh on subsequent calls
    return r;
}

// ---------------------------------------------------------------------------
// Embedding: x[b,t,:] = tok_emb[id] + pos_emb[t] + context_emb[b]
// grid = BTOK blocks, 256 threads, float4 per thread
// ---------------------------------------------------------------------------
__global__ void embed_k(const int* __restrict__ ids,
                        const float* __restrict__ tok,
                        const float* __restrict__ pos,
                        const float* __restrict__ ctx,
                        float* __restrict__ x) {
    const int bt = blockIdx.x;
    const int b  = bt / TT;
    const int t  = bt - b * TT;
    const int id = ids[bt];
    const int d  = threadIdx.x * 4;
    const float4 a = *(const float4*)(tok + (size_t)id * DM + d);
    const float4 p = *(const float4*)(pos + (size_t)t  * DM + d);
    const float4 c = *(const float4*)(ctx + (size_t)b  * DM + d);
    float4 r;
    r.x = a.x + p.x + c.x; r.y = a.y + p.y + c.y;
    r.z = a.z + p.z + c.z; r.w = a.w + p.w + c.w;
    *(float4*)(x + (size_t)bt * DM + d) = r;
}

// ---------------------------------------------------------------------------
// LayerNorm over last dim D=1024. One block (256 threads) per row.
// ---------------------------------------------------------------------------
__global__ void layernorm_k(const float* __restrict__ xin,
                            float* __restrict__ yout,
                            const float* __restrict__ w,
                            const float* __restrict__ b) {
    const size_t row = blockIdx.x;
    const float* xr = xin + row * DM;
    float*       yr = yout + row * DM;
    const int d = threadIdx.x * 4;

    const float4 v = *(const float4*)(xr + d);
    float s  = v.x + v.y + v.z + v.w;
    float s2 = v.x*v.x + v.y*v.y + v.z*v.z + v.w*v.w;
    s  = block_reduce<false>(s);
    s2 = block_reduce<false>(s2);
    const float mean = s * (1.0f / DM);
    const float var  = s2 * (1.0f / DM) - mean * mean;
    const float rstd = rsqrtf(var + 1e-5f);

    const float4 ww = *(const float4*)(w + d);
    const float4 bb = *(const float4*)(b + d);
    float4 r;
    r.x = (v.x - mean) * rstd * ww.x + bb.x;
    r.y = (v.y - mean) * rstd * ww.y + bb.y;
    r.z = (v.z - mean) * rstd * ww.z + bb.z;
    r.w = (v.w - mean) * rstd * ww.w + bb.w;
    *(float4*)(yr + d) = r;
}

// ---------------------------------------------------------------------------
// Generic fp32 GEMM:  C[m,n] = epilogue( scale * sum_k A[m,k]*B(n,k) )
//   BTR=true : B(n,k) = B[n*ldb + k]   (NT: weight matrices [N,K] row-major)
//   BTR=false: B(n,k) = B[k*ldb + n]   (NN: P@V)
// Per-z (batch*head) pointer offsets: off = (z/nheads)*s?b + (z%nheads)*s?h
// causal_mode: 0 none; 1 skip tiles strictly above diagonal (scores);
//              2 clip K loop to m0+BM (P@V with zeroed upper triangle)
// Epilogue: *scale, +bias[n], optional exact GELU, optional residual add.
// All call sites use M%BM==0, N%BN==0, K%BK==0 (verified statically by shapes).
// ---------------------------------------------------------------------------
template <int BM, int BN, int BK, int TM, int TN, int NTH, bool BTR, bool DOGELU>
__global__ __launch_bounds__(NTH, 2)
void gemm_k(const float* __restrict__ A, long lda, long sAb, long sAh,
            const float* __restrict__ B, long ldb, long sBb, long sBh,
            float* __restrict__ C,       long ldc, long sCb, long sCh,
            int M, int N, int K, int nheads,
            const float* __restrict__ bias,
            const float* __restrict__ resid,
            float scale, int causal_mode) {
    const int z  = blockIdx.z;
    const int bb = z / nheads;
    const int hh = z - bb * nheads;
    A += (size_t)bb * sAb + (size_t)hh * sAh;
    B += (size_t)bb * sBb + (size_t)hh * sBh;
    const size_t coff = (size_t)bb * sCb + (size_t)hh * sCh;
    C += coff;
    if (resid) resid += coff;

    const int m0 = blockIdx.y * BM;
    const int n0 = blockIdx.x * BN;
    if (causal_mode == 1 && n0 > m0 + BM - 1) return;   // fully masked tile
    int Keff = K;
    if (causal_mode == 2) Keff = min(K, m0 + BM);       // P is 0 beyond row idx

    __shared__ float As[BK][BM + 4];
    __shared__ float Bs[BK][BN + 4];

    const int tid = threadIdx.x;
    const int tx  = tid % (BN / TN);
    const int ty  = tid / (BN / TN);

    float acc[TM][TN];
#pragma unroll
    for (int i = 0; i < TM; i++)
#pragma unroll
        for (int j = 0; j < TN; j++) acc[i][j] = 0.0f;

    for (int k0 = 0; k0 < Keff; k0 += BK) {
        // --- load A tile (BM x BK), transpose into As[BK][BM] ---
#pragma unroll
        for (int i = tid; i < BM * BK / 4; i += NTH) {
            const int r  = i / (BK / 4);
            const int c4 = i - r * (BK / 4);
            const float4 v = *(const float4*)(A + (size_t)(m0 + r) * lda + k0 + c4 * 4);
            As[c4 * 4 + 0][r] = v.x;
            As[c4 * 4 + 1][r] = v.y;
            As[c4 * 4 + 2][r] = v.z;
            As[c4 * 4 + 3][r] = v.w;
        }
        // --- load B tile into Bs[BK][BN] ---
        if (BTR) {
#pragma unroll
            for (int i = tid; i < BN * BK / 4; i += NTH) {
                const int r  = i / (BK / 4);
                const int c4 = i - r * (BK / 4);
                const float4 v = *(const float4*)(B + (size_t)(n0 + r) * ldb + k0 + c4 * 4);
                Bs[c4 * 4 + 0][r] = v.x;
                Bs[c4 * 4 + 1][r] = v.y;
                Bs[c4 * 4 + 2][r] = v.z;
                Bs[c4 * 4 + 3][r] = v.w;
            }
        } else {
#pragma unroll
            for (int i = tid; i < BK * BN / 4; i += NTH) {
                const int r  = i / (BN / 4);
                const int c4 = i - r * (BN / 4);
                const float4 v = *(const float4*)(B + (size_t)(k0 + r) * ldb + n0 + c4 * 4);
                *(float4*)&Bs[r][c4 * 4] = v;
            }
        }
        __syncthreads();

#pragma unroll
        for (int k = 0; k < BK; k++) {
            float a[TM], bf[TN];
#pragma unroll
            for (int i = 0; i < TM; i += 4)
                *(float4*)&a[i] = *(const float4*)&As[k][ty * TM + i];
#pragma unroll
            for (int j = 0; j < TN; j += 4)
                *(float4*)&bf[j] = *(const float4*)&Bs[k][tx * TN + j];
#pragma unroll
            for (int i = 0; i < TM; i++)
#pragma unroll
                for (int j = 0; j < TN; j++)
                    acc[i][j] = fmaf(a[i], bf[j], acc[i][j]);
        }
        __syncthreads();
    }

    // --- epilogue ---
#pragma unroll
    for (int i = 0; i < TM; i++) {
        const int m = m0 + ty * TM + i;
#pragma unroll
        for (int j = 0; j < TN; j++) {
            const int n = n0 + tx * TN + j;
            float v = acc[i][j] * scale;
            if (bias)  v += bias[n];
            if (DOGELU) v = gelu_exact(v);
            if (resid) v += resid[(size_t)m * ldc + n];
            C[(size_t)m * ldc + n] = v;
        }
    }
}

// ---------------------------------------------------------------------------
// Causal softmax in place over scores rows. grid=(T, B*H), 256 threads.
// Normalizes j in [0, i]; writes 0 for j in (i, T) so P@V can run dense tiles.
// ---------------------------------------------------------------------------
__global__ void softmax_k(float* __restrict__ S) {
    const int  i = blockIdx.x;
    const long z = blockIdx.y;
    float* row = S + (z * (long)TT + i) * (long)TT;
    const int len = i + 1;

    float m = -3.4e38f;
    for (int j = threadIdx.x; j < len; j += blockDim.x) m = fmaxf(m, row[j]);
    m = block_reduce<true>(m);

    float s = 0.0f;
    for (int j = threadIdx.x; j < len; j += blockDim.x) {
        const float e = __expf(row[j] - m);
        row[j] = e;
        s += e;
    }
    s = block_reduce<false>(s);
    const float inv = 1.0f / s;

    for (int j = threadIdx.x; j < len; j += blockDim.x) row[j] *= inv;
    for (int j = len + threadIdx.x; j < TT; j += blockDim.x) row[j] = 0.0f;
}

// ---------------------------------------------------------------------------
// Host orchestration
// ---------------------------------------------------------------------------
extern "C" void kernel_launch(void* const* d_in, const int* in_sizes, int n_in,
                              void* d_out, int out_size) {
    (void)in_sizes; (void)n_in; (void)out_size;
    const int*   ids   = (const int*)  d_in[0];
    const float* ctx   = (const float*)d_in[1];
    const float* tok   = (const float*)d_in[2];
    const float* pos   = (const float*)d_in[3];
    const float* qkvw  = (const float*)d_in[4];
    const float* qkvb  = (const float*)d_in[5];
    const float* projw = (const float*)d_in[6];
    const float* projb = (const float*)d_in[7];
    const float* ln1w  = (const float*)d_in[8];
    const float* ln1b  = (const float*)d_in[9];
    const float* ln2w  = (const float*)d_in[10];
    const float* ln2b  = (const float*)d_in[11];
    const float* f1w   = (const float*)d_in[12];
    const float* f1b   = (const float*)d_in[13];
    const float* f2w   = (const float*)d_in[14];
    const float* f2b   = (const float*)d_in[15];
    const float* lnfw  = (const float*)d_in[16];
    const float* lnfb  = (const float*)d_in[17];
    float* out = (float*)d_out;

    float *x, *h, *qkv, *attn, *mid, *sc;
    cudaGetSymbolAddress((void**)&x,    g_x);
    cudaGetSymbolAddress((void**)&h,    g_h);
    cudaGetSymbolAddress((void**)&qkv,  g_qkv);
    cudaGetSymbolAddress((void**)&attn, g_attn);
    cudaGetSymbolAddress((void**)&mid,  g_mid);
    cudaGetSymbolAddress((void**)&sc,   g_sc);

    const float attn_scale = 0.125f;  // 1/sqrt(64)

    embed_k<<<BTOK, 256>>>(ids, tok, pos, ctx, x);

    for (int l = 0; l < LAYERS; l++) {
        // ln1
        layernorm_k<<<BTOK, 256>>>(x, h, ln1w + (size_t)l * DM, ln1b + (size_t)l * DM);

        // qkv = h @ qkv_w^T + qkv_b      [4096, 3072]
        gemm_k<128,128,16,8,8,256,true,false><<<dim3(3*DM/128, BTOK/128, 1), 256>>>(
            h, DM, 0, 0,
            qkvw + (size_t)l * 3 * DM * DM, DM, 0, 0,
            qkv, 3*DM, 0, 0,
            BTOK, 3*DM, DM, 1,
            qkvb + (size_t)l * 3 * DM, nullptr, 1.0f, 0);

        // scores[z] = scale * Q @ K^T   (skip upper-triangle tiles)
        gemm_k<128,128,16,8,8,256,true,false><<<dim3(TT/128, TT/128, BBATCH*NH), 256>>>(
            qkv,        3*DM, (long)TT*3*DM, HDIM,
            qkv + DM,   3*DM, (long)TT*3*DM, HDIM,
            sc, TT, (long)NH*TT*TT, (long)TT*TT,
            TT, TT, HDIM, NH,
            nullptr, nullptr, attn_scale, 1);

        // causal softmax (zeros upper triangle)
        softmax_k<<<dim3(TT, BBATCH*NH), 256>>>(sc);

        // attn[z] = P @ V   (K loop clipped to m0+BM)
        gemm_k<128,64,16,8,4,256,false,false><<<dim3(1, TT/128, BBATCH*NH), 256>>>(
            sc, TT, (long)NH*TT*TT, (long)TT*TT,
            qkv + 2*DM, 3*DM, (long)TT*3*DM, HDIM,
            attn, DM, (long)TT*DM, HDIM,
            TT, HDIM, TT, NH,
            nullptr, nullptr, 1.0f, 2);

        // x += attn @ proj_w^T + proj_b
        gemm_k<128,128,16,8,8,256,true,false><<<dim3(DM/128, BTOK/128, 1), 256>>>(
            attn, DM, 0, 0,
            projw + (size_t)l * DM * DM, DM, 0, 0,
            x, DM, 0, 0,
            BTOK, DM, DM, 1,
            projb + (size_t)l * DM, x, 1.0f, 0);

        // ln2
        layernorm_k<<<BTOK, 256>>>(x, h, ln2w + (size_t)l * DM, ln2b + (size_t)l * DM);

        // mid = gelu(h @ f1_w^T + f1_b)   [4096, 4096]
        gemm_k<128,128,16,8,8,256,true,true><<<dim3(4*DM/128, BTOK/128, 1), 256>>>(
            h, DM, 0, 0,
            f1w + (size_t)l * 4 * DM * DM, DM, 0, 0,
            mid, 4*DM, 0, 0,
            BTOK, 4*DM, DM, 1,
            f1b + (size_t)l * 4 * DM, nullptr, 1.0f, 0);

        // x += mid @ f2_w^T + f2_b
        gemm_k<128,128,16,8,8,256,true,false><<<dim3(DM/128, BTOK/128, 1), 256>>>(
            mid, 4*DM, 0, 0,
            f2w + (size_t)l * DM * 4 * DM, 4*DM, 0, 0,
            x, DM, 0, 0,
            BTOK, DM, 4*DM, 1,
            f2b + (size_t)l * DM, x, 1.0f, 0);
    }

    // final layernorm
    layernorm_k<<<BTOK, 256>>>(x, h, lnfw, lnfb);

    // logits = h @ tok_emb^T   [4096, 32000]
    gemm_k<128,128,16,8,8,256,true,false><<<dim3(VO/128, BTOK/128, 1), 256>>>(
        h, DM, 0, 0,
        tok, DM, 0, 0,
        out, VO, 0, 0,
        BTOK, VO, DM, 1,
        nullptr, nullptr, 1.0f, 0);
}